// round 16
// baseline (speedup 1.0000x reference)
#include <cuda_runtime.h>
#include <cuda_bf16.h>
#include <cstdint>

// Problem constants
#define BB 4096
#define SS 31
#define CC 512
#define HH 8
#define HD 64
#define M_TOT (BB*SS)        // 126976
#define NPOS (SS*SS)         // 961
#define BH (BB*HH)           // 32768
#define EPS 1e-5f
#define INV_SQRT_C 0.044194173824159216f   // 1/sqrt(512)
#define NPART 992            // BN1 partial blocks

// ---------------- scratch (static device memory; no allocations) ----------------
__device__ __align__(16) __nv_bfloat16 g_xb[(size_t)M_TOT * 512];    // BN(x), hi only
__device__ __align__(16) __nv_bfloat16 g_ctxb[(size_t)M_TOT * 512];  // ctx, plain bf16
// Weights packed: per row 16 chunks of [32 hi | 32 lo] bf16 (128 B/chunk).
__device__ __align__(16) __nv_bfloat16 g_wp[(size_t)1536 * 1024];
__device__ __align__(16) __nv_bfloat16 g_wop[(size_t)512 * 1024];

__device__ __align__(16) __nv_bfloat16 g_qb[(size_t)M_TOT * CC];
__device__ __align__(16) __nv_bfloat16 g_kb[(size_t)M_TOT * CC];
__device__ __align__(16) float g_vf[(size_t)M_TOT * CC];             // v in fp32
__device__ __align__(16) __nv_bfloat16 g_energy[(size_t)BH * NPOS];  // energy bf16

// BN1 two-phase partials (no atomics)
__device__ __align__(16) float g_psum[(size_t)NPART * CC];
__device__ __align__(16) float g_psq[(size_t)NPART * CC];
__device__ __align__(16) float g_scale[CC];
__device__ __align__(16) float g_shift[CC];
__device__ __align__(16) float g_p_sum[NPOS];
__device__ __align__(16) float g_p_sq[NPOS];
__device__ __align__(16) float g_sc2[NPOS];
__device__ __align__(16) float g_sh2[NPOS];

// ---------------- helpers ----------------
__device__ __forceinline__ uint32_t smem_u32(const void* p) {
    uint32_t a;
    asm("{ .reg .u64 t; cvta.to.shared.u64 t, %1; cvt.u32.u64 %0, t; }" : "=r"(a) : "l"(p));
    return a;
}
__device__ __forceinline__ void cp16(uint32_t dst, const void* src) {
    asm volatile("cp.async.cg.shared.global [%0], [%1], 16;" :: "r"(dst), "l"(src) : "memory");
}
__device__ __forceinline__ void cp_commit() {
    asm volatile("cp.async.commit_group;" ::: "memory");
}
__device__ __forceinline__ void cp_wait1() {
    asm volatile("cp.async.wait_group 1;" ::: "memory");
}
__device__ __forceinline__ void cp_wait0() {
    asm volatile("cp.async.wait_group 0;" ::: "memory");
}
__device__ __forceinline__ void ldsm_x4(uint32_t* r, uint32_t addr) {
    asm volatile("ldmatrix.sync.aligned.m8n8.x4.shared.b16 {%0,%1,%2,%3}, [%4];"
                 : "=r"(r[0]), "=r"(r[1]), "=r"(r[2]), "=r"(r[3]) : "r"(addr));
}
__device__ __forceinline__ void mma16816(float* c, const uint32_t* a, const uint32_t* b) {
    asm volatile(
        "mma.sync.aligned.m16n8k16.row.col.f32.bf16.bf16.f32 "
        "{%0,%1,%2,%3}, {%4,%5,%6,%7}, {%8,%9}, {%0,%1,%2,%3};"
        : "+f"(c[0]), "+f"(c[1]), "+f"(c[2]), "+f"(c[3])
        : "r"(a[0]), "r"(a[1]), "r"(a[2]), "r"(a[3]), "r"(b[0]), "r"(b[1]));
}
#define SWZ(off) ((off) ^ (((off) >> 3) & 0x70u))

// ---------------- launch #1: BN1 partial stats + weight split (packed) --------------
__global__ void __launch_bounds__(256) k_pre1(const float* __restrict__ x,
                                              const float* __restrict__ Wq,
                                              const float* __restrict__ Wk,
                                              const float* __restrict__ Wv,
                                              const float* __restrict__ Wo) {
    const int tid = threadIdx.x;
    const int blk = blockIdx.x;
    if (blk < NPART) {
        const size_t r0 = (size_t)blk * 128;
        const float* xp = x + r0 * CC;
        float s0 = 0.f, s1 = 0.f, q0 = 0.f, q1 = 0.f;
        for (int r = 0; r < 128; r++) {
            float v0 = xp[(size_t)r * CC + tid];
            float v1 = xp[(size_t)r * CC + tid + 256];
            s0 += v0; q0 += v0 * v0;
            s1 += v1; q1 += v1 * v1;
        }
        g_psum[(size_t)blk * CC + tid]       = s0;
        g_psq [(size_t)blk * CC + tid]       = q0;
        g_psum[(size_t)blk * CC + tid + 256] = s1;
        g_psq [(size_t)blk * CC + tid + 256] = q1;
    } else {
        int t = (blk - NPART) * 256 + tid;   // [0, 131072)
        int row = t >> 6;
        int oct = t & 63;
        int c = oct >> 2, pos = (oct & 3) << 3, k = oct << 3;
        const float* src;
        __nv_bfloat16* dst;
        if (row < 1536) {
            src = (row < 512) ? (Wq + (size_t)row * 512)
                : (row < 1024) ? (Wk + (size_t)(row - 512) * 512)
                               : (Wv + (size_t)(row - 1024) * 512);
            dst = g_wp + (((size_t)row * 16 + c) << 6) + pos;
        } else {
            int r2 = row - 1536;
            src = Wo + (size_t)r2 * 512;
            dst = g_wop + (((size_t)r2 * 16 + c) << 6) + pos;
        }
        float4 a = *(const float4*)(src + k);
        float4 b = *(const float4*)(src + k + 4);
        float v[8] = {a.x, a.y, a.z, a.w, b.x, b.y, b.z, b.w};
        __nv_bfloat16 hi[8], lo[8];
#pragma unroll
        for (int i = 0; i < 8; i++) {
            hi[i] = __float2bfloat16(v[i]);
            lo[i] = __float2bfloat16(v[i] - __bfloat162float(hi[i]));
        }
        *(uint4*)dst        = *(uint4*)hi;
        *(uint4*)(dst + 32) = *(uint4*)lo;
    }
}

// ---------------- launch #2: BN1 finalize (block per channel) + zero BN2 buffers ----
__global__ void __launch_bounds__(256) k_pre2(const float* __restrict__ nw,
                                              const float* __restrict__ nb) {
    const int blk = blockIdx.x, tid = threadIdx.x;   // <<<516, 256>>>
    if (blk < CC) {
        __shared__ float ss[8], sq[8];
        float s = 0.f, q = 0.f;
        for (int p = tid; p < NPART; p += 256) {
            s += g_psum[(size_t)p * CC + blk];
            q += g_psq [(size_t)p * CC + blk];
        }
#pragma unroll
        for (int off = 16; off > 0; off >>= 1) {
            s += __shfl_xor_sync(0xFFFFFFFFu, s, off);
            q += __shfl_xor_sync(0xFFFFFFFFu, q, off);
        }
        if ((tid & 31) == 0) { ss[tid >> 5] = s; sq[tid >> 5] = q; }
        __syncthreads();
        if (tid == 0) {
            float S = 0.f, Q = 0.f;
#pragma unroll
            for (int i = 0; i < 8; i++) { S += ss[i]; Q += sq[i]; }
            const float inv_n = 1.0f / (float)M_TOT;
            float mean = S * inv_n;
            float var  = Q * inv_n - mean * mean;
            float rs   = rsqrtf(var + EPS);
            float sc   = rs * nw[blk];
            g_scale[blk] = sc;
            g_shift[blk] = nb[blk] - mean * sc;
        }
    } else {
        int i = (blk - CC) * 256 + tid;
        if (i < NPOS) { g_p_sum[i] = 0.f; g_p_sq[i] = 0.f; }
    }
}

// ---------------- launch #3: xn = BN(x) -> plain bf16 ----------------
__global__ void __launch_bounds__(256) k_split_x(const float* __restrict__ x) {
    size_t t = (size_t)blockIdx.x * 256 + threadIdx.x;
    size_t m = t >> 6;
    int k = (int)(t & 63) * 8;
    const float* xp = x + m * 512 + k;
    float4 a  = *(const float4*)xp;
    float4 b  = *(const float4*)(xp + 4);
    float4 sA = *(const float4*)(g_scale + k);
    float4 sB = *(const float4*)(g_scale + k + 4);
    float4 hA = *(const float4*)(g_shift + k);
    float4 hB = *(const float4*)(g_shift + k + 4);
    __nv_bfloat16 hb[8];
    hb[0] = __float2bfloat16(fmaf(a.x, sA.x, hA.x));
    hb[1] = __float2bfloat16(fmaf(a.y, sA.y, hA.y));
    hb[2] = __float2bfloat16(fmaf(a.z, sA.z, hA.z));
    hb[3] = __float2bfloat16(fmaf(a.w, sA.w, hA.w));
    hb[4] = __float2bfloat16(fmaf(b.x, sB.x, hB.x));
    hb[5] = __float2bfloat16(fmaf(b.y, sB.y, hB.y));
    hb[6] = __float2bfloat16(fmaf(b.z, sB.z, hB.z));
    hb[7] = __float2bfloat16(fmaf(b.w, sB.w, hB.w));
    *(uint4*)(g_xb + m * 512 + k) = *(uint4*)hb;
}

// ---------------- 1-term GEMM: 2-stage (R13/R14 equilibrium config) ----------------
// MODE 0: A = g_xb, B = g_wp rows [0,1024) -> q/k bf16
// MODE 1: A = g_ctxb, B = g_wop -> out = D + bias + resid (fp32)
template<int MODE>
__global__ void __launch_bounds__(128) k_gemm_1t(const float* __restrict__ bias,
                                                 const float* __restrict__ resid,
                                                 float* __restrict__ Dout) {
    extern __shared__ char sm[];  // 2 stages x (A 16KB + B 16KB) = 64KB
    const int tid = threadIdx.x, lane = tid & 31, w = tid >> 5;
    const int wm = w >> 1, wn = w & 1;
    const int m0 = blockIdx.y * 128, n0g = blockIdx.x * 128;
    const __nv_bfloat16* Asrc = (MODE == 0) ? g_xb : g_ctxb;
    const __nv_bfloat16* Bsrc = (MODE == 0) ? g_wp : g_wop;
    const uint32_t sbase = smem_u32(sm);

    float c[4][8][4];
#pragma unroll
    for (int i = 0; i < 4; i++)
#pragma unroll
        for (int j = 0; j < 8; j++)
#pragma unroll
            for (int l = 0; l < 4; l++) c[i][j][l] = 0.f;

    const int a_row = lane & 15;
    const int a_cb  = (lane >> 4) * 16;
    const int b_row = (lane & 7) + ((lane >> 4) & 1) * 8;
    const int b_cb  = ((lane >> 3) & 1) * 16;

    auto load_stage = [&](int st, int s) {
        uint32_t abase = sbase + st * 32768;
        uint32_t bbase = abase + 16384;
#pragma unroll
        for (int j = 0; j < 8; j++) {
            int u = j * 128 + tid, r = u >> 3, q8 = u & 7;
            cp16(abase + SWZ((uint32_t)(r * 128 + q8 * 16)),
                 Asrc + (size_t)(m0 + r) * 512 + 64 * s + q8 * 8);
        }
#pragma unroll
        for (int j = 0; j < 8; j++) {
            int u = j * 128 + tid, r = u >> 3, q8 = u & 7;
            cp16(bbase + SWZ((uint32_t)(r * 128 + q8 * 16)),
                 Bsrc + (((size_t)(n0g + r) * 16 + 2 * s + (q8 >> 2)) << 6) + (q8 & 3) * 8);
        }
        cp_commit();
    };

    load_stage(0, 0);

    for (int it = 0; it < 8; it++) {
        if (it + 1 < 8) { load_stage((it + 1) & 1, it + 1); cp_wait1(); }
        else            { cp_wait0(); }
        __syncthreads();

        const uint32_t abase = sbase + (it & 1) * 32768;
        const uint32_t bbase = abase + 16384;

#pragma unroll
        for (int ks = 0; ks < 4; ks++) {
            uint32_t ah[16], bh[16];
#pragma unroll
            for (int mi = 0; mi < 4; mi++)
                ldsm_x4(&ah[mi * 4],
                        abase + SWZ((uint32_t)((wm * 64 + mi * 16 + a_row) * 128 + ks * 32 + a_cb)));
#pragma unroll
            for (int nt = 0; nt < 4; nt++)
                ldsm_x4(&bh[nt * 4],
                        bbase + SWZ((uint32_t)((wn * 64 + nt * 16 + b_row) * 128 + ks * 32 + b_cb)));
#pragma unroll
            for (int mi = 0; mi < 4; mi++)
#pragma unroll
                for (int nj = 0; nj < 8; nj++)
                    mma16816(c[mi][nj], &ah[mi * 4], &bh[nj * 2]);
        }
        __syncthreads();
    }

    const int r1 = lane >> 2;
    const int c0 = (lane & 3) * 2;
#pragma unroll
    for (int mi = 0; mi < 4; mi++) {
        const int gr = m0 + wm * 64 + mi * 16;
#pragma unroll
        for (int nj = 0; nj < 8; nj++) {
            const int gc = n0g + wn * 64 + nj * 8 + c0;
            if (MODE == 0) {
                const int sel = gc >> 9;
                const int col = gc & 511;
                __nv_bfloat16* op = (sel == 0) ? g_qb : g_kb;
                *(__nv_bfloat162*)(op + (size_t)(gr + r1) * 512 + col) =
                    __floats2bfloat162_rn(c[mi][nj][0], c[mi][nj][1]);
                *(__nv_bfloat162*)(op + (size_t)(gr + r1 + 8) * 512 + col) =
                    __floats2bfloat162_rn(c[mi][nj][2], c[mi][nj][3]);
            } else {
                const int col = gc;
                const float b0 = bias[col], b1 = bias[col + 1];
                {
                    const size_t off = (size_t)(gr + r1) * 512 + col;
                    float2 rv = *(const float2*)(resid + off);
                    *(float2*)(Dout + off) =
                        make_float2(c[mi][nj][0] + b0 + rv.x, c[mi][nj][1] + b1 + rv.y);
                }
                {
                    const size_t off = (size_t)(gr + r1 + 8) * 512 + col;
                    float2 rv = *(const float2*)(resid + off);
                    *(float2*)(Dout + off) =
                        make_float2(c[mi][nj][2] + b0 + rv.x, c[mi][nj][3] + b1 + rv.y);
                }
            }
        }
    }
}

// ---------------- v GEMM: 2-term (Ah*Bh + Ah*Bl), 3-stage, v stored fp32 ----------
__global__ void __launch_bounds__(128) k_gemm_v() {
    extern __shared__ char sm[];  // 3 x (10240 + 16384) = 79872
    const int tid = threadIdx.x, lane = tid & 31, w = tid >> 5;
    const int wm = w >> 1, wn = w & 1;
    const int m0 = blockIdx.y * 128, nb = blockIdx.x * 128;
    const uint32_t sbase = smem_u32(sm);

    float c[4][8][4];
#pragma unroll
    for (int i = 0; i < 4; i++)
#pragma unroll
        for (int j = 0; j < 8; j++)
#pragma unroll
            for (int l = 0; l < 4; l++) c[i][j][l] = 0.f;

    const int a_row = lane & 15;
    const int a_cb  = (lane >> 4) * 16;
    const int b_row = (lane & 7) + ((lane >> 4) & 1) * 8;
    const int b_cb  = ((lane >> 3) & 1) * 16;

    auto load_stage = [&](int st, int ch) {
        uint32_t abase = sbase + st * 26624;
        uint32_t bbase = abase + 10240;
#pragma unroll
        for (int j = 0; j < 4; j++) {
            int u = j * 128 + tid, r = u >> 2, q8 = u & 3;
            cp16(abase + (uint32_t)(r * 80 + q8 * 16),
                 g_xb + (size_t)(m0 + r) * 512 + 32 * ch + q8 * 8);
        }
#pragma unroll
        for (int j = 0; j < 8; j++) {
            int u = j * 128 + tid, r = u >> 3, q8 = u & 7;
            cp16(bbase + SWZ((uint32_t)(r * 128 + q8 * 16)),
                 g_wp + (((size_t)(1024 + nb + r) * 16 + ch) << 6) + q8 * 8);
        }
        cp_commit();
    };

    load_stage(0, 0);
    load_stage(1, 1);

    int stg = 0;
    for (int it = 0; it < 16; it++) {
        if (it + 1 < 16) cp_wait1(); else cp_wait0();
        __syncthreads();

        const uint32_t abase = sbase + stg * 26624;
        const uint32_t bbase = abase + 10240;

#pragma unroll
        for (int ks = 0; ks < 2; ks++) {
            uint32_t ah[16], bh[16], bl[16];
#pragma unroll
            for (int mi = 0; mi < 4; mi++)
                ldsm_x4(&ah[mi * 4],
                        abase + (uint32_t)((wm * 64 + mi * 16 + a_row) * 80 + ks * 32 + a_cb));
#pragma unroll
            for (int nt = 0; nt < 4; nt++)
                ldsm_x4(&bh[nt * 4],
                        bbase + SWZ((uint32_t)((wn * 64 + nt * 16 + b_row) * 128 + ks * 32 + b_cb)));
#pragma unroll
            for (int mi = 0; mi < 4; mi++)
#pragma unroll
                for (int nj = 0; nj < 8; nj++)
                    mma16816(c[mi][nj], &ah[mi * 4], &bh[nj * 2]);
#pragma unroll
            for (int nt = 0; nt < 4; nt++)
                ldsm_x4(&bl[nt * 4],
                        bbase + SWZ((uint32_t)((wn * 64 + nt * 16 + b_row) * 128 + 64 + ks * 32 + b_cb)));
#pragma unroll
            for (int mi = 0; mi < 4; mi++)
#pragma unroll
                for (int nj = 0; nj < 8; nj++)
                    mma16816(c[mi][nj], &ah[mi * 4], &bl[nj * 2]);
        }
        if (it + 2 < 16) load_stage((stg + 2) % 3, it + 2);
        stg = (stg + 1) % 3;
    }

    const int r1 = lane >> 2;
    const int c0 = (lane & 3) * 2;
#pragma unroll
    for (int mi = 0; mi < 4; mi++) {
        const int gr = m0 + wm * 64 + mi * 16;
#pragma unroll
        for (int nj = 0; nj < 8; nj++) {
            const int col = nb + wn * 64 + nj * 8 + c0;
            *(float2*)(g_vf + (size_t)(gr + r1) * 512 + col) =
                make_float2(c[mi][nj][0], c[mi][nj][1]);
            *(float2*)(g_vf + (size_t)(gr + r1 + 8) * 512 + col) =
                make_float2(c[mi][nj][2], c[mi][nj][3]);
        }
    }
}

// ---------------- energy via bf16 MMA + fused BN2 partials; energy stored bf16 ------
#define ET_ROWB 144
#define ET_SZ  (32 * ET_ROWB)
#define E_SMEM (16 * ET_SZ)            // 73728 B

__global__ void __launch_bounds__(256) k_energy_mma() {
    extern __shared__ char sm[];
    const int tid = threadIdx.x, lane = tid & 31, w = tid >> 5;   // w = head
    const int b = blockIdx.x;
    const uint32_t sbase = smem_u32(sm);
    const uint32_t qt = sbase + w * ET_SZ;
    const uint32_t kt = sbase + 8 * ET_SZ + w * ET_SZ;

    const __nv_bfloat16* qsrc = g_qb + (size_t)(b * SS) * 512 + w * 64;
    const __nv_bfloat16* ksrc = g_kb + (size_t)(b * SS) * 512 + w * 64;
    for (int i = lane; i < 248; i += 32) {
        int row = i >> 3, q8 = i & 7;
        cp16(qt + row * ET_ROWB + q8 * 16, qsrc + (size_t)row * 512 + q8 * 8);
        cp16(kt + row * ET_ROWB + q8 * 16, ksrc + (size_t)row * 512 + q8 * 8);
    }
    cp_commit();
    cp_wait0();
    if (lane < 16) {
        uint32_t base = (lane < 8) ? qt : kt;
        int q8 = lane & 7;
        uint4 z = make_uint4(0u, 0u, 0u, 0u);
        *(uint4*)(sm + (base - sbase) + 31 * ET_ROWB + q8 * 16) = z;
    }
    __syncthreads();

    float c[2][4][4];
#pragma unroll
    for (int i = 0; i < 2; i++)
#pragma unroll
        for (int j = 0; j < 4; j++)
#pragma unroll
            for (int l = 0; l < 4; l++) c[i][j][l] = 0.f;

    const int a_row = lane & 15;
    const int a_cb  = (lane >> 4) * 16;
    const int b_row = (lane & 7) + ((lane >> 4) & 1) * 8;
    const int b_cb  = ((lane >> 3) & 1) * 16;

#pragma unroll
    for (int ks = 0; ks < 4; ks++) {
        uint32_t af[2][4], bf[8];
#pragma unroll
        for (int mi = 0; mi < 2; mi++)
            ldsm_x4(af[mi], qt + (mi * 16 + a_row) * ET_ROWB + ks * 32 + a_cb);
#pragma unroll
        for (int g = 0; g < 2; g++)
            ldsm_x4(&bf[g * 4], kt + (g * 16 + b_row) * ET_ROWB + ks * 32 + b_cb);
#pragma unroll
        for (int mi = 0; mi < 2; mi++)
#pragma unroll
            for (int nj = 0; nj < 4; nj++)
                mma16816(c[mi][nj], af[mi], &bf[nj * 2]);
    }
    __syncthreads();

    float* stage = (float*)sm;
    const int r0 = lane >> 2, c0 = (lane & 3) * 2;
#pragma unroll
    for (int mi = 0; mi < 2; mi++)
#pragma unroll
        for (int nj = 0; nj < 4; nj++) {
            int rr = mi * 16 + r0, cc = nj * 8 + c0;
            stage[w * 1024 + rr * 32 + cc]           = c[mi][nj][0];
            stage[w * 1024 + rr * 32 + cc + 1]       = c[mi][nj][1];
            stage[w * 1024 + (rr + 8) * 32 + cc]     = c[mi][nj][2];
            stage[w * 1024 + (rr + 8) * 32 + cc + 1] = c[mi][nj][3];
        }
    __syncthreads();

    __nv_bfloat16* ebase = g_energy + (size_t)(b * 8) * NPOS;
    for (int p = tid; p < NPOS; p += 256) {
        int r = p / SS, cph = p - r * SS;
        int idx = r * 32 + cph;
        float s = 0.f, q = 0.f;
#pragma unroll
        for (int h = 0; h < 8; h++) {
            float v = stage[h * 1024 + idx];
            ebase[(size_t)h * NPOS + p] = __float2bfloat16(v);
            s += v; q += v * v;
        }
        atomicAdd(&g_p_sum[p], s);
        atomicAdd(&g_p_sq[p],  q);
    }
}

// ---------------- BN2 finalize ----------------
__global__ void k_bn2_fin(const float* __restrict__ pw, const float* __restrict__ pb) {
    int i = blockIdx.x * blockDim.x + threadIdx.x;
    if (i >= NPOS) return;
    float inv_n = 1.0f / (float)BH;
    float mean = g_p_sum[i] * inv_n;
    float var  = g_p_sq[i] * inv_n - mean * mean;
    float rs   = rsqrtf(var + EPS);
    float a    = rs * pw[i] * INV_SQRT_C;
    g_sc2[i] = a;
    g_sh2[i] = pb[i] * INV_SQRT_C - mean * a;
}

// ---------------- softmax (poly exp, logits bounded by BN2) + AV (3-term) -----------
#define AT_SMEM 77824

__global__ void __launch_bounds__(128) k_attn_mma() {
    extern __shared__ char smA[];
    const int tid = threadIdx.x, lane = tid & 31, w = tid >> 5;
    const int b = blockIdx.x >> 1;
    const int h = ((blockIdx.x & 1) << 2) + w;
    const uint32_t sbase = smem_u32(smA);
    char* e_t   = smA + w * 4096;
    char* phi_p = smA + 16384 + w * 2560;
    char* plo_p = smA + 26624 + w * 2560;
    char* vh_p  = smA + 36864 + w * 5120;
    char* vl_p  = smA + 57344 + w * 5120;
    const uint32_t phi = sbase + 16384 + w * 2560;
    const uint32_t plo = sbase + 26624 + w * 2560;
    const uint32_t vh  = sbase + 36864 + w * 5120;
    const uint32_t vl  = sbase + 57344 + w * 5120;

    for (int i = lane; i < 640; i += 32) {
        ((uint32_t*)phi_p)[i] = 0u;
        ((uint32_t*)plo_p)[i] = 0u;
    }
    for (int d = lane; d < 64; d += 32) {
        *(__nv_bfloat16*)(vh_p + d * 80 + 62) = __float2bfloat16(0.f);
        *(__nv_bfloat16*)(vl_p + d * 80 + 62) = __float2bfloat16(0.f);
    }

    const __nv_bfloat16* ep = g_energy + (size_t)(b * 8 + h) * NPOS;
    for (int p = lane; p < NPOS; p += 32) {
        float v = fmaf(__bfloat162float(ep[p]), g_sc2[p], g_sh2[p]);
        int r = p / SS, cc = p - r * SS;
        ((float*)e_t)[r * 33 + cc] = v;
    }
    const float* vp = g_vf + (size_t)(b * SS) * 512 + h * 64;
    for (int i = lane; i < SS * 16; i += 32) {
        int s = i >> 4, d0 = (i & 15) << 2;
        float4 vv = *(const float4*)(vp + (size_t)s * 512 + d0);
        float arr[4] = {vv.x, vv.y, vv.z, vv.w};
#pragma unroll
        for (int j = 0; j < 4; j++) {
            __nv_bfloat16 hi = __float2bfloat16(arr[j]);
            __nv_bfloat16 lo = __float2bfloat16(arr[j] - __bfloat162float(hi));
            *(__nv_bfloat16*)(vh_p + (d0 + j) * 80 + s * 2) = hi;
            *(__nv_bfloat16*)(vl_p + (d0 + j) * 80 + s * 2) = lo;
        }
    }
    __syncwarp();

    // softmax without max-subtraction: BN2 + 1/sqrt(C) bound |logit| <~ 0.3,
    // so e^t is computed by a degree-5 Taylor (rel err < 3e-5); ratios cancel
    // residual common error.
    if (lane < SS) {
        float* row = (float*)e_t + lane * 33;
        float sum = 0.f;
#pragma unroll
        for (int cc = 0; cc < SS; cc++) {
            float t = row[cc];
            float e = 1.f + t * (1.f + t * (0.5f + t * (0.16666667f +
                      t * (0.041666667f + t * 0.0083333333f))));
            row[cc] = e; sum += e;
        }
        float inv = 1.0f / sum;
#pragma unroll
        for (int cc = 0; cc < SS; cc++) {
            float p = row[cc] * inv;
            __nv_bfloat16 hi = __float2bfloat16(p);
            __nv_bfloat16 lo = __float2bfloat16(p - __bfloat162float(hi));
            *(__nv_bfloat16*)(phi_p + lane * 80 + cc * 2) = hi;
            *(__nv_bfloat16*)(plo_p + lane * 80 + cc * 2) = lo;
        }
    }
    __syncwarp();

    float acc[2][8][4];
#pragma unroll
    for (int i = 0; i < 2; i++)
#pragma unroll
        for (int j = 0; j < 8; j++)
#pragma unroll
            for (int l = 0; l < 4; l++) acc[i][j][l] = 0.f;

    const int a_row = lane & 15;
    const int a_cb  = (lane >> 4) * 16;
    const int b_row = (lane & 7) + ((lane >> 4) & 1) * 8;
    const int b_cb  = ((lane >> 3) & 1) * 16;

#pragma unroll
    for (int ks = 0; ks < 2; ks++) {
        uint32_t pf[2][4], lf[2][4], bh[16], bl[16];
#pragma unroll
        for (int mi = 0; mi < 2; mi++) {
            ldsm_x4(pf[mi], phi + (mi * 16 + a_row) * 80 + ks * 32 + a_cb);
            ldsm_x4(lf[mi], plo + (mi * 16 + a_row) * 80 + ks * 32 + a_cb);
        }
#pragma unroll
        for (int nt = 0; nt < 4; nt++) {
            ldsm_x4(&bh[nt * 4], vh + (nt * 16 + b_row) * 80 + ks * 32 + b_cb);
            ldsm_x4(&bl[nt * 4], vl + (nt * 16 + b_row) * 80 + ks * 32 + b_cb);
        }
#pragma unroll
        for (int mi = 0; mi < 2; mi++)
#pragma unroll
            for (int nj = 0; nj < 8; nj++)
                mma16816(acc[mi][nj], pf[mi], &bh[nj * 2]);
#pragma unroll
        for (int mi = 0; mi < 2; mi++)
#pragma unroll
            for (int nj = 0; nj < 8; nj++)
                mma16816(acc[mi][nj], lf[mi], &bh[nj * 2]);
#pragma unroll
        for (int mi = 0; mi < 2; mi++)
#pragma unroll
            for (int nj = 0; nj < 8; nj++)
                mma16816(acc[mi][nj], pf[mi], &bl[nj * 2]);
    }

    const int r1 = lane >> 2, c0 = (lane & 3) * 2;
#pragma unroll
    for (int mi = 0; mi < 2; mi++) {
#pragma unroll
        for (int nj = 0; nj < 8; nj++) {
            const int d = nj * 8 + c0;
            const int colg = h * 64 + d;
            const int q1 = mi * 16 + r1;
            const int q2 = q1 + 8;
            *(__nv_bfloat162*)(g_ctxb + ((size_t)b * 31 + q1) * 512 + colg) =
                __floats2bfloat162_rn(acc[mi][nj][0], acc[mi][nj][1]);
            if (q2 < 31)
                *(__nv_bfloat162*)(g_ctxb + ((size_t)b * 31 + q2) * 512 + colg) =
                    __floats2bfloat162_rn(acc[mi][nj][2], acc[mi][nj][3]);
        }
    }
}

// ---------------- launch ----------------
extern "C" void kernel_launch(void* const* d_in, const int* in_sizes, int n_in,
                              void* d_out, int out_size) {
    const float* x     = (const float*)d_in[0];
    const float* nw    = (const float*)d_in[1];
    const float* nbias = (const float*)d_in[2];
    const float* Wq    = (const float*)d_in[3];
    const float* Wk    = (const float*)d_in[4];
    const float* Wv    = (const float*)d_in[5];
    const float* Wout  = (const float*)d_in[6];
    const float* b_out = (const float*)d_in[7];
    const float* pw    = (const float*)d_in[8];
    const float* pb    = (const float*)d_in[9];
    float* out = (float*)d_out;

    cudaFuncSetAttribute(k_gemm_1t<0>, cudaFuncAttributeMaxDynamicSharedMemorySize, 65536);
    cudaFuncSetAttribute(k_gemm_1t<1>, cudaFuncAttributeMaxDynamicSharedMemorySize, 65536);
    cudaFuncSetAttribute(k_gemm_v, cudaFuncAttributeMaxDynamicSharedMemorySize, 79872);
    cudaFuncSetAttribute(k_energy_mma, cudaFuncAttributeMaxDynamicSharedMemorySize, E_SMEM);
    cudaFuncSetAttribute(k_attn_mma, cudaFuncAttributeMaxDynamicSharedMemorySize, AT_SMEM);

    k_pre1<<<NPART + 512, 256>>>(x, Wq, Wk, Wv, Wout);            // #1
    k_pre2<<<CC + 4, 256>>>(nw, nbias);                           // #2
    k_split_x<<<M_TOT / 4, 256>>>(x);                             // #3
    k_gemm_1t<0><<<dim3(8, 992), 128, 65536>>>(nullptr, nullptr, nullptr);  // #4 <- ncu
    k_gemm_v<<<dim3(4, 992), 128, 79872>>>();                     // #5
    k_energy_mma<<<BB, 256, E_SMEM>>>();                          // #6
    k_bn2_fin<<<4, 256>>>(pw, pb);                                // #7
    k_attn_mma<<<BB * 2, 128, AT_SMEM>>>();                       // #8
    k_gemm_1t<1><<<dim3(4, 992), 128, 65536>>>(b_out, x, out);    // #9
}

// round 17
// speedup vs baseline: 1.4225x; 1.4225x over previous
#include <cuda_runtime.h>
#include <cuda_bf16.h>
#include <cstdint>

// Problem constants
#define BB 4096
#define SS 31
#define CC 512
#define HH 8
#define HD 64
#define M_TOT (BB*SS)        // 126976
#define NPOS (SS*SS)         // 961
#define BH (BB*HH)           // 32768
#define EPS 1e-5f
#define INV_SQRT_C 0.044194173824159216f   // 1/sqrt(512)
#define NPART 992            // BN1 partial blocks

// ---------------- scratch (static device memory; no allocations) ----------------
__device__ __align__(16) __nv_bfloat16 g_xb[(size_t)M_TOT * 512];    // BN(x), hi only
__device__ __align__(16) __nv_bfloat16 g_ctxb[(size_t)M_TOT * 512];  // ctx, plain bf16
// Weights packed: per row 16 chunks of [32 hi | 32 lo] bf16 (128 B/chunk).
__device__ __align__(16) __nv_bfloat16 g_wp[(size_t)1536 * 1024];
__device__ __align__(16) __nv_bfloat16 g_wop[(size_t)512 * 1024];

__device__ __align__(16) __nv_bfloat16 g_qb[(size_t)M_TOT * CC];
__device__ __align__(16) __nv_bfloat16 g_kb[(size_t)M_TOT * CC];
__device__ __align__(16) float g_vf[(size_t)M_TOT * CC];             // v in fp32
__device__ __align__(16) __nv_bfloat16 g_energy[(size_t)BH * NPOS];  // energy bf16

// BN1 two-phase partials (no atomics)
__device__ __align__(16) float g_psum[(size_t)NPART * CC];
__device__ __align__(16) float g_psq[(size_t)NPART * CC];
__device__ __align__(16) float g_scale[CC];
__device__ __align__(16) float g_shift[CC];
__device__ __align__(16) float g_p_sum[NPOS];
__device__ __align__(16) float g_p_sq[NPOS];
__device__ __align__(16) float g_sc2[NPOS];
__device__ __align__(16) float g_sh2[NPOS];

// ---------------- helpers ----------------
__device__ __forceinline__ uint32_t smem_u32(const void* p) {
    uint32_t a;
    asm("{ .reg .u64 t; cvta.to.shared.u64 t, %1; cvt.u32.u64 %0, t; }" : "=r"(a) : "l"(p));
    return a;
}
__device__ __forceinline__ void cp16(uint32_t dst, const void* src) {
    asm volatile("cp.async.cg.shared.global [%0], [%1], 16;" :: "r"(dst), "l"(src) : "memory");
}
__device__ __forceinline__ void cp_commit() {
    asm volatile("cp.async.commit_group;" ::: "memory");
}
__device__ __forceinline__ void cp_wait1() {
    asm volatile("cp.async.wait_group 1;" ::: "memory");
}
__device__ __forceinline__ void cp_wait0() {
    asm volatile("cp.async.wait_group 0;" ::: "memory");
}
__device__ __forceinline__ void ldsm_x4(uint32_t* r, uint32_t addr) {
    asm volatile("ldmatrix.sync.aligned.m8n8.x4.shared.b16 {%0,%1,%2,%3}, [%4];"
                 : "=r"(r[0]), "=r"(r[1]), "=r"(r[2]), "=r"(r[3]) : "r"(addr));
}
__device__ __forceinline__ void mma16816(float* c, const uint32_t* a, const uint32_t* b) {
    asm volatile(
        "mma.sync.aligned.m16n8k16.row.col.f32.bf16.bf16.f32 "
        "{%0,%1,%2,%3}, {%4,%5,%6,%7}, {%8,%9}, {%0,%1,%2,%3};"
        : "+f"(c[0]), "+f"(c[1]), "+f"(c[2]), "+f"(c[3])
        : "r"(a[0]), "r"(a[1]), "r"(a[2]), "r"(a[3]), "r"(b[0]), "r"(b[1]));
}
#define SWZ(off) ((off) ^ (((off) >> 3) & 0x70u))

// ---------------- launch #1: BN1 partial stats + weight split (packed) --------------
__global__ void __launch_bounds__(256) k_pre1(const float* __restrict__ x,
                                              const float* __restrict__ Wq,
                                              const float* __restrict__ Wk,
                                              const float* __restrict__ Wv,
                                              const float* __restrict__ Wo) {
    const int tid = threadIdx.x;
    const int blk = blockIdx.x;
    if (blk < NPART) {
        const size_t r0 = (size_t)blk * 128;
        const float* xp = x + r0 * CC;
        float s0 = 0.f, s1 = 0.f, q0 = 0.f, q1 = 0.f;
        for (int r = 0; r < 128; r++) {
            float v0 = xp[(size_t)r * CC + tid];
            float v1 = xp[(size_t)r * CC + tid + 256];
            s0 += v0; q0 += v0 * v0;
            s1 += v1; q1 += v1 * v1;
        }
        g_psum[(size_t)blk * CC + tid]       = s0;
        g_psq [(size_t)blk * CC + tid]       = q0;
        g_psum[(size_t)blk * CC + tid + 256] = s1;
        g_psq [(size_t)blk * CC + tid + 256] = q1;
    } else {
        int t = (blk - NPART) * 256 + tid;   // [0, 131072)
        int row = t >> 6;
        int oct = t & 63;
        int c = oct >> 2, pos = (oct & 3) << 3, k = oct << 3;
        const float* src;
        __nv_bfloat16* dst;
        if (row < 1536) {
            src = (row < 512) ? (Wq + (size_t)row * 512)
                : (row < 1024) ? (Wk + (size_t)(row - 512) * 512)
                               : (Wv + (size_t)(row - 1024) * 512);
            dst = g_wp + (((size_t)row * 16 + c) << 6) + pos;
        } else {
            int r2 = row - 1536;
            src = Wo + (size_t)r2 * 512;
            dst = g_wop + (((size_t)r2 * 16 + c) << 6) + pos;
        }
        float4 a = *(const float4*)(src + k);
        float4 b = *(const float4*)(src + k + 4);
        float v[8] = {a.x, a.y, a.z, a.w, b.x, b.y, b.z, b.w};
        __nv_bfloat16 hi[8], lo[8];
#pragma unroll
        for (int i = 0; i < 8; i++) {
            hi[i] = __float2bfloat16(v[i]);
            lo[i] = __float2bfloat16(v[i] - __bfloat162float(hi[i]));
        }
        *(uint4*)dst        = *(uint4*)hi;
        *(uint4*)(dst + 32) = *(uint4*)lo;
    }
}

// ---------------- launch #2: BN1 finalize (block per channel) + zero BN2 buffers ----
__global__ void __launch_bounds__(256) k_pre2(const float* __restrict__ nw,
                                              const float* __restrict__ nb) {
    const int blk = blockIdx.x, tid = threadIdx.x;   // <<<516, 256>>>
    if (blk < CC) {
        __shared__ float ss[8], sq[8];
        float s = 0.f, q = 0.f;
        for (int p = tid; p < NPART; p += 256) {
            s += g_psum[(size_t)p * CC + blk];
            q += g_psq [(size_t)p * CC + blk];
        }
#pragma unroll
        for (int off = 16; off > 0; off >>= 1) {
            s += __shfl_xor_sync(0xFFFFFFFFu, s, off);
            q += __shfl_xor_sync(0xFFFFFFFFu, q, off);
        }
        if ((tid & 31) == 0) { ss[tid >> 5] = s; sq[tid >> 5] = q; }
        __syncthreads();
        if (tid == 0) {
            float S = 0.f, Q = 0.f;
#pragma unroll
            for (int i = 0; i < 8; i++) { S += ss[i]; Q += sq[i]; }
            const float inv_n = 1.0f / (float)M_TOT;
            float mean = S * inv_n;
            float var  = Q * inv_n - mean * mean;
            float rs   = rsqrtf(var + EPS);
            float sc   = rs * nw[blk];
            g_scale[blk] = sc;
            g_shift[blk] = nb[blk] - mean * sc;
        }
    } else {
        int i = (blk - CC) * 256 + tid;
        if (i < NPOS) { g_p_sum[i] = 0.f; g_p_sq[i] = 0.f; }
    }
}

// ---------------- launch #3: xn = BN(x) -> plain bf16 ----------------
__global__ void __launch_bounds__(256) k_split_x(const float* __restrict__ x) {
    size_t t = (size_t)blockIdx.x * 256 + threadIdx.x;
    size_t m = t >> 6;
    int k = (int)(t & 63) * 8;
    const float* xp = x + m * 512 + k;
    float4 a  = *(const float4*)xp;
    float4 b  = *(const float4*)(xp + 4);
    float4 sA = *(const float4*)(g_scale + k);
    float4 sB = *(const float4*)(g_scale + k + 4);
    float4 hA = *(const float4*)(g_shift + k);
    float4 hB = *(const float4*)(g_shift + k + 4);
    __nv_bfloat16 hb[8];
    hb[0] = __float2bfloat16(fmaf(a.x, sA.x, hA.x));
    hb[1] = __float2bfloat16(fmaf(a.y, sA.y, hA.y));
    hb[2] = __float2bfloat16(fmaf(a.z, sA.z, hA.z));
    hb[3] = __float2bfloat16(fmaf(a.w, sA.w, hA.w));
    hb[4] = __float2bfloat16(fmaf(b.x, sB.x, hB.x));
    hb[5] = __float2bfloat16(fmaf(b.y, sB.y, hB.y));
    hb[6] = __float2bfloat16(fmaf(b.z, sB.z, hB.z));
    hb[7] = __float2bfloat16(fmaf(b.w, sB.w, hB.w));
    *(uint4*)(g_xb + m * 512 + k) = *(uint4*)hb;
}

// ---------------- 1-term GEMM: 2-stage (R13/R14 equilibrium config) ----------------
// MODE 0: A = g_xb, B = g_wp rows [0,1024) -> q/k bf16
// MODE 1: A = g_ctxb, B = g_wop -> out = D + bias + resid (fp32)
template<int MODE>
__global__ void __launch_bounds__(128) k_gemm_1t(const float* __restrict__ bias,
                                                 const float* __restrict__ resid,
                                                 float* __restrict__ Dout) {
    extern __shared__ char sm[];  // 2 stages x (A 16KB + B 16KB) = 64KB
    const int tid = threadIdx.x, lane = tid & 31, w = tid >> 5;
    const int wm = w >> 1, wn = w & 1;
    const int m0 = blockIdx.y * 128, n0g = blockIdx.x * 128;
    const __nv_bfloat16* Asrc = (MODE == 0) ? g_xb : g_ctxb;
    const __nv_bfloat16* Bsrc = (MODE == 0) ? g_wp : g_wop;
    const uint32_t sbase = smem_u32(sm);

    float c[4][8][4];
#pragma unroll
    for (int i = 0; i < 4; i++)
#pragma unroll
        for (int j = 0; j < 8; j++)
#pragma unroll
            for (int l = 0; l < 4; l++) c[i][j][l] = 0.f;

    const int a_row = lane & 15;
    const int a_cb  = (lane >> 4) * 16;
    const int b_row = (lane & 7) + ((lane >> 4) & 1) * 8;
    const int b_cb  = ((lane >> 3) & 1) * 16;

    auto load_stage = [&](int st, int s) {
        uint32_t abase = sbase + st * 32768;
        uint32_t bbase = abase + 16384;
#pragma unroll
        for (int j = 0; j < 8; j++) {
            int u = j * 128 + tid, r = u >> 3, q8 = u & 7;
            cp16(abase + SWZ((uint32_t)(r * 128 + q8 * 16)),
                 Asrc + (size_t)(m0 + r) * 512 + 64 * s + q8 * 8);
        }
#pragma unroll
        for (int j = 0; j < 8; j++) {
            int u = j * 128 + tid, r = u >> 3, q8 = u & 7;
            cp16(bbase + SWZ((uint32_t)(r * 128 + q8 * 16)),
                 Bsrc + (((size_t)(n0g + r) * 16 + 2 * s + (q8 >> 2)) << 6) + (q8 & 3) * 8);
        }
        cp_commit();
    };

    load_stage(0, 0);

    for (int it = 0; it < 8; it++) {
        if (it + 1 < 8) { load_stage((it + 1) & 1, it + 1); cp_wait1(); }
        else            { cp_wait0(); }
        __syncthreads();

        const uint32_t abase = sbase + (it & 1) * 32768;
        const uint32_t bbase = abase + 16384;

#pragma unroll
        for (int ks = 0; ks < 4; ks++) {
            uint32_t ah[16], bh[16];
#pragma unroll
            for (int mi = 0; mi < 4; mi++)
                ldsm_x4(&ah[mi * 4],
                        abase + SWZ((uint32_t)((wm * 64 + mi * 16 + a_row) * 128 + ks * 32 + a_cb)));
#pragma unroll
            for (int nt = 0; nt < 4; nt++)
                ldsm_x4(&bh[nt * 4],
                        bbase + SWZ((uint32_t)((wn * 64 + nt * 16 + b_row) * 128 + ks * 32 + b_cb)));
#pragma unroll
            for (int mi = 0; mi < 4; mi++)
#pragma unroll
                for (int nj = 0; nj < 8; nj++)
                    mma16816(c[mi][nj], &ah[mi * 4], &bh[nj * 2]);
        }
        __syncthreads();
    }

    const int r1 = lane >> 2;
    const int c0 = (lane & 3) * 2;
#pragma unroll
    for (int mi = 0; mi < 4; mi++) {
        const int gr = m0 + wm * 64 + mi * 16;
#pragma unroll
        for (int nj = 0; nj < 8; nj++) {
            const int gc = n0g + wn * 64 + nj * 8 + c0;
            if (MODE == 0) {
                const int sel = gc >> 9;
                const int col = gc & 511;
                __nv_bfloat16* op = (sel == 0) ? g_qb : g_kb;
                *(__nv_bfloat162*)(op + (size_t)(gr + r1) * 512 + col) =
                    __floats2bfloat162_rn(c[mi][nj][0], c[mi][nj][1]);
                *(__nv_bfloat162*)(op + (size_t)(gr + r1 + 8) * 512 + col) =
                    __floats2bfloat162_rn(c[mi][nj][2], c[mi][nj][3]);
            } else {
                const int col = gc;
                const float b0 = bias[col], b1 = bias[col + 1];
                {
                    const size_t off = (size_t)(gr + r1) * 512 + col;
                    float2 rv = *(const float2*)(resid + off);
                    *(float2*)(Dout + off) =
                        make_float2(c[mi][nj][0] + b0 + rv.x, c[mi][nj][1] + b1 + rv.y);
                }
                {
                    const size_t off = (size_t)(gr + r1 + 8) * 512 + col;
                    float2 rv = *(const float2*)(resid + off);
                    *(float2*)(Dout + off) =
                        make_float2(c[mi][nj][2] + b0 + rv.x, c[mi][nj][3] + b1 + rv.y);
                }
            }
        }
    }
}

// ---------------- v GEMM: 2-term (Ah*Bh + Ah*Bl), 3-stage, v stored fp32 ----------
__global__ void __launch_bounds__(128) k_gemm_v() {
    extern __shared__ char sm[];  // 3 x (10240 + 16384) = 79872
    const int tid = threadIdx.x, lane = tid & 31, w = tid >> 5;
    const int wm = w >> 1, wn = w & 1;
    const int m0 = blockIdx.y * 128, nb = blockIdx.x * 128;
    const uint32_t sbase = smem_u32(sm);

    float c[4][8][4];
#pragma unroll
    for (int i = 0; i < 4; i++)
#pragma unroll
        for (int j = 0; j < 8; j++)
#pragma unroll
            for (int l = 0; l < 4; l++) c[i][j][l] = 0.f;

    const int a_row = lane & 15;
    const int a_cb  = (lane >> 4) * 16;
    const int b_row = (lane & 7) + ((lane >> 4) & 1) * 8;
    const int b_cb  = ((lane >> 3) & 1) * 16;

    auto load_stage = [&](int st, int ch) {
        uint32_t abase = sbase + st * 26624;
        uint32_t bbase = abase + 10240;
#pragma unroll
        for (int j = 0; j < 4; j++) {
            int u = j * 128 + tid, r = u >> 2, q8 = u & 3;
            cp16(abase + (uint32_t)(r * 80 + q8 * 16),
                 g_xb + (size_t)(m0 + r) * 512 + 32 * ch + q8 * 8);
        }
#pragma unroll
        for (int j = 0; j < 8; j++) {
            int u = j * 128 + tid, r = u >> 3, q8 = u & 7;
            cp16(bbase + SWZ((uint32_t)(r * 128 + q8 * 16)),
                 g_wp + (((size_t)(1024 + nb + r) * 16 + ch) << 6) + q8 * 8);
        }
        cp_commit();
    };

    load_stage(0, 0);
    load_stage(1, 1);

    int stg = 0;
    for (int it = 0; it < 16; it++) {
        if (it + 1 < 16) cp_wait1(); else cp_wait0();
        __syncthreads();

        const uint32_t abase = sbase + stg * 26624;
        const uint32_t bbase = abase + 10240;

#pragma unroll
        for (int ks = 0; ks < 2; ks++) {
            uint32_t ah[16], bh[16], bl[16];
#pragma unroll
            for (int mi = 0; mi < 4; mi++)
                ldsm_x4(&ah[mi * 4],
                        abase + (uint32_t)((wm * 64 + mi * 16 + a_row) * 80 + ks * 32 + a_cb));
#pragma unroll
            for (int nt = 0; nt < 4; nt++)
                ldsm_x4(&bh[nt * 4],
                        bbase + SWZ((uint32_t)((wn * 64 + nt * 16 + b_row) * 128 + ks * 32 + b_cb)));
#pragma unroll
            for (int mi = 0; mi < 4; mi++)
#pragma unroll
                for (int nj = 0; nj < 8; nj++)
                    mma16816(c[mi][nj], &ah[mi * 4], &bh[nj * 2]);
#pragma unroll
            for (int nt = 0; nt < 4; nt++)
                ldsm_x4(&bl[nt * 4],
                        bbase + SWZ((uint32_t)((wn * 64 + nt * 16 + b_row) * 128 + 64 + ks * 32 + b_cb)));
#pragma unroll
            for (int mi = 0; mi < 4; mi++)
#pragma unroll
                for (int nj = 0; nj < 8; nj++)
                    mma16816(c[mi][nj], &ah[mi * 4], &bl[nj * 2]);
        }
        if (it + 2 < 16) load_stage((stg + 2) % 3, it + 2);
        stg = (stg + 1) % 3;
    }

    const int r1 = lane >> 2;
    const int c0 = (lane & 3) * 2;
#pragma unroll
    for (int mi = 0; mi < 4; mi++) {
        const int gr = m0 + wm * 64 + mi * 16;
#pragma unroll
        for (int nj = 0; nj < 8; nj++) {
            const int col = nb + wn * 64 + nj * 8 + c0;
            *(float2*)(g_vf + (size_t)(gr + r1) * 512 + col) =
                make_float2(c[mi][nj][0], c[mi][nj][1]);
            *(float2*)(g_vf + (size_t)(gr + r1 + 8) * 512 + col) =
                make_float2(c[mi][nj][2], c[mi][nj][3]);
        }
    }
}

// ---------------- energy via bf16 MMA + fused BN2 partials; energy stored bf16 ------
#define ET_ROWB 144
#define ET_SZ  (32 * ET_ROWB)
#define E_SMEM (16 * ET_SZ)            // 73728 B

__global__ void __launch_bounds__(256) k_energy_mma() {
    extern __shared__ char sm[];
    const int tid = threadIdx.x, lane = tid & 31, w = tid >> 5;   // w = head
    const int b = blockIdx.x;
    const uint32_t sbase = smem_u32(sm);
    const uint32_t qt = sbase + w * ET_SZ;
    const uint32_t kt = sbase + 8 * ET_SZ + w * ET_SZ;

    const __nv_bfloat16* qsrc = g_qb + (size_t)(b * SS) * 512 + w * 64;
    const __nv_bfloat16* ksrc = g_kb + (size_t)(b * SS) * 512 + w * 64;
    for (int i = lane; i < 248; i += 32) {
        int row = i >> 3, q8 = i & 7;
        cp16(qt + row * ET_ROWB + q8 * 16, qsrc + (size_t)row * 512 + q8 * 8);
        cp16(kt + row * ET_ROWB + q8 * 16, ksrc + (size_t)row * 512 + q8 * 8);
    }
    cp_commit();
    cp_wait0();
    if (lane < 16) {
        uint32_t base = (lane < 8) ? qt : kt;
        int q8 = lane & 7;
        uint4 z = make_uint4(0u, 0u, 0u, 0u);
        *(uint4*)(sm + (base - sbase) + 31 * ET_ROWB + q8 * 16) = z;
    }
    __syncthreads();

    float c[2][4][4];
#pragma unroll
    for (int i = 0; i < 2; i++)
#pragma unroll
        for (int j = 0; j < 4; j++)
#pragma unroll
            for (int l = 0; l < 4; l++) c[i][j][l] = 0.f;

    const int a_row = lane & 15;
    const int a_cb  = (lane >> 4) * 16;
    const int b_row = (lane & 7) + ((lane >> 4) & 1) * 8;
    const int b_cb  = ((lane >> 3) & 1) * 16;

#pragma unroll
    for (int ks = 0; ks < 4; ks++) {
        uint32_t af[2][4], bf[8];
#pragma unroll
        for (int mi = 0; mi < 2; mi++)
            ldsm_x4(af[mi], qt + (mi * 16 + a_row) * ET_ROWB + ks * 32 + a_cb);
#pragma unroll
        for (int g = 0; g < 2; g++)
            ldsm_x4(&bf[g * 4], kt + (g * 16 + b_row) * ET_ROWB + ks * 32 + b_cb);
#pragma unroll
        for (int mi = 0; mi < 2; mi++)
#pragma unroll
            for (int nj = 0; nj < 4; nj++)
                mma16816(c[mi][nj], af[mi], &bf[nj * 2]);
    }
    __syncthreads();

    float* stage = (float*)sm;
    const int r0 = lane >> 2, c0 = (lane & 3) * 2;
#pragma unroll
    for (int mi = 0; mi < 2; mi++)
#pragma unroll
        for (int nj = 0; nj < 4; nj++) {
            int rr = mi * 16 + r0, cc = nj * 8 + c0;
            stage[w * 1024 + rr * 32 + cc]           = c[mi][nj][0];
            stage[w * 1024 + rr * 32 + cc + 1]       = c[mi][nj][1];
            stage[w * 1024 + (rr + 8) * 32 + cc]     = c[mi][nj][2];
            stage[w * 1024 + (rr + 8) * 32 + cc + 1] = c[mi][nj][3];
        }
    __syncthreads();

    __nv_bfloat16* ebase = g_energy + (size_t)(b * 8) * NPOS;
    for (int p = tid; p < NPOS; p += 256) {
        int r = p / SS, cph = p - r * SS;
        int idx = r * 32 + cph;
        float s = 0.f, q = 0.f;
#pragma unroll
        for (int h = 0; h < 8; h++) {
            float v = stage[h * 1024 + idx];
            ebase[(size_t)h * NPOS + p] = __float2bfloat16(v);
            s += v; q += v * v;
        }
        atomicAdd(&g_p_sum[p], s);
        atomicAdd(&g_p_sq[p],  q);
    }
}

// ---------------- BN2 finalize ----------------
__global__ void k_bn2_fin(const float* __restrict__ pw, const float* __restrict__ pb) {
    int i = blockIdx.x * blockDim.x + threadIdx.x;
    if (i >= NPOS) return;
    float inv_n = 1.0f / (float)BH;
    float mean = g_p_sum[i] * inv_n;
    float var  = g_p_sq[i] * inv_n - mean * mean;
    float rs   = rsqrtf(var + EPS);
    float a    = rs * pw[i] * INV_SQRT_C;
    g_sc2[i] = a;
    g_sh2[i] = pb[i] * INV_SQRT_C - mean * a;
}

// ---------------- softmax (poly exp, logits bounded by BN2) + AV (3-term) -----------
#define AT_SMEM 77824

__global__ void __launch_bounds__(128) k_attn_mma() {
    extern __shared__ char smA[];
    const int tid = threadIdx.x, lane = tid & 31, w = tid >> 5;
    const int b = blockIdx.x >> 1;
    const int h = ((blockIdx.x & 1) << 2) + w;
    const uint32_t sbase = smem_u32(smA);
    char* e_t   = smA + w * 4096;
    char* phi_p = smA + 16384 + w * 2560;
    char* plo_p = smA + 26624 + w * 2560;
    char* vh_p  = smA + 36864 + w * 5120;
    char* vl_p  = smA + 57344 + w * 5120;
    const uint32_t phi = sbase + 16384 + w * 2560;
    const uint32_t plo = sbase + 26624 + w * 2560;
    const uint32_t vh  = sbase + 36864 + w * 5120;
    const uint32_t vl  = sbase + 57344 + w * 5120;

    for (int i = lane; i < 640; i += 32) {
        ((uint32_t*)phi_p)[i] = 0u;
        ((uint32_t*)plo_p)[i] = 0u;
    }
    for (int d = lane; d < 64; d += 32) {
        *(__nv_bfloat16*)(vh_p + d * 80 + 62) = __float2bfloat16(0.f);
        *(__nv_bfloat16*)(vl_p + d * 80 + 62) = __float2bfloat16(0.f);
    }

    const __nv_bfloat16* ep = g_energy + (size_t)(b * 8 + h) * NPOS;
    for (int p = lane; p < NPOS; p += 32) {
        float v = fmaf(__bfloat162float(ep[p]), g_sc2[p], g_sh2[p]);
        int r = p / SS, cc = p - r * SS;
        ((float*)e_t)[r * 33 + cc] = v;
    }
    const float* vp = g_vf + (size_t)(b * SS) * 512 + h * 64;
    for (int i = lane; i < SS * 16; i += 32) {
        int s = i >> 4, d0 = (i & 15) << 2;
        float4 vv = *(const float4*)(vp + (size_t)s * 512 + d0);
        float arr[4] = {vv.x, vv.y, vv.z, vv.w};
#pragma unroll
        for (int j = 0; j < 4; j++) {
            __nv_bfloat16 hi = __float2bfloat16(arr[j]);
            __nv_bfloat16 lo = __float2bfloat16(arr[j] - __bfloat162float(hi));
            *(__nv_bfloat16*)(vh_p + (d0 + j) * 80 + s * 2) = hi;
            *(__nv_bfloat16*)(vl_p + (d0 + j) * 80 + s * 2) = lo;
        }
    }
    __syncwarp();

    // softmax without max-subtraction: BN2 + 1/sqrt(C) bound |logit| <~ 0.3,
    // so e^t is computed by a degree-5 Taylor (rel err < 3e-5); ratios cancel
    // residual common error.
    if (lane < SS) {
        float* row = (float*)e_t + lane * 33;
        float sum = 0.f;
#pragma unroll
        for (int cc = 0; cc < SS; cc++) {
            float t = row[cc];
            float e = 1.f + t * (1.f + t * (0.5f + t * (0.16666667f +
                      t * (0.041666667f + t * 0.0083333333f))));
            row[cc] = e; sum += e;
        }
        float inv = 1.0f / sum;
#pragma unroll
        for (int cc = 0; cc < SS; cc++) {
            float p = row[cc] * inv;
            __nv_bfloat16 hi = __float2bfloat16(p);
            __nv_bfloat16 lo = __float2bfloat16(p - __bfloat162float(hi));
            *(__nv_bfloat16*)(phi_p + lane * 80 + cc * 2) = hi;
            *(__nv_bfloat16*)(plo_p + lane * 80 + cc * 2) = lo;
        }
    }
    __syncwarp();

    float acc[2][8][4];
#pragma unroll
    for (int i = 0; i < 2; i++)
#pragma unroll
        for (int j = 0; j < 8; j++)
#pragma unroll
            for (int l = 0; l < 4; l++) acc[i][j][l] = 0.f;

    const int a_row = lane & 15;
    const int a_cb  = (lane >> 4) * 16;
    const int b_row = (lane & 7) + ((lane >> 4) & 1) * 8;
    const int b_cb  = ((lane >> 3) & 1) * 16;

#pragma unroll
    for (int ks = 0; ks < 2; ks++) {
        uint32_t pf[2][4], lf[2][4], bh[16], bl[16];
#pragma unroll
        for (int mi = 0; mi < 2; mi++) {
            ldsm_x4(pf[mi], phi + (mi * 16 + a_row) * 80 + ks * 32 + a_cb);
            ldsm_x4(lf[mi], plo + (mi * 16 + a_row) * 80 + ks * 32 + a_cb);
        }
#pragma unroll
        for (int nt = 0; nt < 4; nt++) {
            ldsm_x4(&bh[nt * 4], vh + (nt * 16 + b_row) * 80 + ks * 32 + b_cb);
            ldsm_x4(&bl[nt * 4], vl + (nt * 16 + b_row) * 80 + ks * 32 + b_cb);
        }
#pragma unroll
        for (int mi = 0; mi < 2; mi++)
#pragma unroll
            for (int nj = 0; nj < 8; nj++)
                mma16816(acc[mi][nj], pf[mi], &bh[nj * 2]);
#pragma unroll
        for (int mi = 0; mi < 2; mi++)
#pragma unroll
            for (int nj = 0; nj < 8; nj++)
                mma16816(acc[mi][nj], lf[mi], &bh[nj * 2]);
#pragma unroll
        for (int mi = 0; mi < 2; mi++)
#pragma unroll
            for (int nj = 0; nj < 8; nj++)
                mma16816(acc[mi][nj], pf[mi], &bl[nj * 2]);
    }

    const int r1 = lane >> 2, c0 = (lane & 3) * 2;
#pragma unroll
    for (int mi = 0; mi < 2; mi++) {
#pragma unroll
        for (int nj = 0; nj < 8; nj++) {
            const int d = nj * 8 + c0;
            const int colg = h * 64 + d;
            const int q1 = mi * 16 + r1;
            const int q2 = q1 + 8;
            *(__nv_bfloat162*)(g_ctxb + ((size_t)b * 31 + q1) * 512 + colg) =
                __floats2bfloat162_rn(acc[mi][nj][0], acc[mi][nj][1]);
            if (q2 < 31)
                *(__nv_bfloat162*)(g_ctxb + ((size_t)b * 31 + q2) * 512 + colg) =
                    __floats2bfloat162_rn(acc[mi][nj][2], acc[mi][nj][3]);
        }
    }
}

// ---------------- launch ----------------
extern "C" void kernel_launch(void* const* d_in, const int* in_sizes, int n_in,
                              void* d_out, int out_size) {
    const float* x     = (const float*)d_in[0];
    const float* nw    = (const float*)d_in[1];
    const float* nbias = (const float*)d_in[2];
    const float* Wq    = (const float*)d_in[3];
    const float* Wk    = (const float*)d_in[4];
    const float* Wv    = (const float*)d_in[5];
    const float* Wout  = (const float*)d_in[6];
    const float* b_out = (const float*)d_in[7];
    const float* pw    = (const float*)d_in[8];
    const float* pb    = (const float*)d_in[9];
    float* out = (float*)d_out;

    cudaFuncSetAttribute(k_gemm_1t<0>, cudaFuncAttributeMaxDynamicSharedMemorySize, 65536);
    cudaFuncSetAttribute(k_gemm_1t<1>, cudaFuncAttributeMaxDynamicSharedMemorySize, 65536);
    cudaFuncSetAttribute(k_gemm_v, cudaFuncAttributeMaxDynamicSharedMemorySize, 79872);
    cudaFuncSetAttribute(k_energy_mma, cudaFuncAttributeMaxDynamicSharedMemorySize, E_SMEM);
    cudaFuncSetAttribute(k_attn_mma, cudaFuncAttributeMaxDynamicSharedMemorySize, AT_SMEM);

    k_pre1<<<NPART + 512, 256>>>(x, Wq, Wk, Wv, Wout);            // #1
    k_pre2<<<CC + 4, 256>>>(nw, nbias);                           // #2
    k_split_x<<<M_TOT / 4, 256>>>(x);                             // #3
    k_gemm_1t<0><<<dim3(8, 992), 128, 65536>>>(nullptr, nullptr, nullptr);  // #4 <- ncu
    k_gemm_v<<<dim3(4, 992), 128, 79872>>>();                     // #5
    k_energy_mma<<<BB, 256, E_SMEM>>>();                          // #6
    k_bn2_fin<<<4, 256>>>(pw, pb);                                // #7
    k_attn_mma<<<BB * 2, 128, AT_SMEM>>>();                       // #8
    k_gemm_1t<1><<<dim3(4, 992), 128, 65536>>>(b_out, x, out);    // #9
}